// round 14
// baseline (speedup 1.0000x reference)
#include <cuda_runtime.h>
#include <math.h>

#define IMG_H 512
#define IMG_W 512
#define NB    64
#define NPIX  (IMG_H * IMG_W)
#define NPEL  (NPIX * 3)
#define RBLK  64
#define ROWF  (IMG_W * 3)
#define P1BLK 256          // pass1/pass2 blocks per image (= NPIX/4/256)

__device__ float g_scratch[(size_t)NB * NPEL];
__device__ float g_partial0[NB * RBLK];
__device__ float g_partial1[NB * P1BLK];
__device__ float g_mean1[NB];

struct F3 { float x, y, z; };

// pointwise transforms applied to each tapped value (layer-0 fused into taps)
struct PWId  {
    __device__ __forceinline__ float operator()(float v) const { return v; }
};
struct PWAff {                       // clip(m + f*(v-m)): contrast; m=0 -> brightness
    float f, m;
    __device__ __forceinline__ float operator()(float v) const {
        return fminf(fmaxf(m + f * (v - m), 0.f), 1.f);
    }
};

__device__ __forceinline__ float inline_mean(const float* __restrict__ part, int b)
{
    float s = 0.f;
    #pragma unroll
    for (int i = 0; i < RBLK; i++) s += part[b * RBLK + i];
    return s * (1.0f / (float)NPEL);
}

// ---------------------------------------------------------------------------
// horizontal 2-tap bilinear (wy == 0 exactly)
// ---------------------------------------------------------------------------
template <class PW>
__device__ __forceinline__ F3 bilin_h(const float* __restrict__ img, float xi, int y,
                                      PW pw)
{
    float x0f = floorf(xi);
    float wx  = xi - x0f;
    float w0  = 1.f - wx;
    int   x0  = (int)x0f;
    const float* row = img + (size_t)y * ROWF;
    F3 r;
    if (x0 >= 0 && x0 < IMG_W - 1) {
        const float* p = row + x0 * 3;
        r.x = w0 * pw(p[0]) + wx * pw(p[3]);
        r.y = w0 * pw(p[1]) + wx * pw(p[4]);
        r.z = w0 * pw(p[2]) + wx * pw(p[5]);
    } else {
        bool v0 = (x0 >= 0)  && (x0 <= IMG_W - 1);
        bool v1 = (x0 >= -1) && (x0 <= IMG_W - 2);
        int xc0 = min(max(x0,     0), IMG_W - 1);
        int xc1 = min(max(x0 + 1, 0), IMG_W - 1);
        const float* p0 = row + xc0 * 3;
        const float* p1 = row + xc1 * 3;
        float a0 = v0 ? pw(p0[0]) : 0.5f, a1 = v0 ? pw(p0[1]) : 0.5f, a2 = v0 ? pw(p0[2]) : 0.5f;
        float b0 = v1 ? pw(p1[0]) : 0.5f, b1 = v1 ? pw(p1[1]) : 0.5f, b2 = v1 ? pw(p1[2]) : 0.5f;
        r.x = w0 * a0 + wx * b0;
        r.y = w0 * a1 + wx * b1;
        r.z = w0 * a2 + wx * b2;
    }
    return r;
}

// ---------------------------------------------------------------------------
// vertical 2-tap bilinear, single output (border/fallback)
// ---------------------------------------------------------------------------
template <class PW>
__device__ __forceinline__ F3 bilin_v(const float* __restrict__ img, float yi, int x,
                                      PW pw)
{
    float y0f = floorf(yi);
    float wy  = yi - y0f;
    float w0  = 1.f - wy;
    int   y0  = (int)y0f;
    F3 r;
    if (y0 >= 0 && y0 < IMG_H - 1) {
        const float* p = img + ((size_t)y0 * IMG_W + x) * 3;
        const float* q = p + ROWF;
        r.x = w0 * pw(p[0]) + wy * pw(q[0]);
        r.y = w0 * pw(p[1]) + wy * pw(q[1]);
        r.z = w0 * pw(p[2]) + wy * pw(q[2]);
    } else {
        bool v0 = (y0 >= 0)  && (y0 <= IMG_H - 1);
        bool v1 = (y0 >= -1) && (y0 <= IMG_H - 2);
        int yc0 = min(max(y0,     0), IMG_H - 1);
        int yc1 = min(max(y0 + 1, 0), IMG_H - 1);
        const float* p0 = img + ((size_t)yc0 * IMG_W + x) * 3;
        const float* p1 = img + ((size_t)yc1 * IMG_W + x) * 3;
        float a0 = v0 ? pw(p0[0]) : 0.5f, a1 = v0 ? pw(p0[1]) : 0.5f, a2 = v0 ? pw(p0[2]) : 0.5f;
        float b0 = v1 ? pw(p1[0]) : 0.5f, b1 = v1 ? pw(p1[1]) : 0.5f, b2 = v1 ? pw(p1[2]) : 0.5f;
        r.x = w0 * a0 + wy * b0;
        r.y = w0 * a1 + wy * b1;
        r.z = w0 * a2 + wy * b2;
    }
    return r;
}

// ---------------------------------------------------------------------------
// quad-row vertical bilinear: 5 tap rows for 4 outputs when aligned
// ---------------------------------------------------------------------------
template <class PW>
__device__ __forceinline__ void bilin_v4(const float* __restrict__ img,
                                         const float yi[4], int x, F3 r[4], PW pw)
{
    float k0f = floorf(yi[0]);
    int   k0  = (int)k0f;
    bool aligned = (k0 >= 0) && (k0 + 4 <= IMG_H - 1);
    #pragma unroll
    for (int i = 1; i < 4; i++)
        aligned = aligned && ((int)floorf(yi[i]) == k0 + i);
    if (aligned) {
        const float* p = img + ((size_t)k0 * IMG_W + x) * 3;
        float rv[5][3];
        #pragma unroll
        for (int j = 0; j < 5; j++) {
            rv[j][0] = pw(p[0]); rv[j][1] = pw(p[1]); rv[j][2] = pw(p[2]);
            p += ROWF;
        }
        #pragma unroll
        for (int i = 0; i < 4; i++) {
            float wy = yi[i] - floorf(yi[i]);
            float w0 = 1.f - wy;
            r[i].x = w0 * rv[i][0] + wy * rv[i+1][0];
            r[i].y = w0 * rv[i][1] + wy * rv[i+1][1];
            r[i].z = w0 * rv[i][2] + wy * rv[i+1][2];
        }
    } else {
        #pragma unroll
        for (int i = 0; i < 4; i++) r[i] = bilin_v(img, yi[i], x, pw);
    }
}

// ---------------------------------------------------------------------------
// general 4-tap bilinear (rotate)
// ---------------------------------------------------------------------------
template <class PW>
__device__ __forceinline__ F3 bilin4(const float* __restrict__ img, float xi, float yi,
                                     PW pw)
{
    float x0f = floorf(xi), y0f = floorf(yi);
    float wx = xi - x0f,    wy = yi - y0f;
    int   x0 = (int)x0f,    y0 = (int)y0f;
    float w00 = (1.f - wx) * (1.f - wy);
    float w10 = wx * (1.f - wy);
    float w01 = (1.f - wx) * wy;
    float w11 = wx * wy;
    F3 r;
    if (x0 >= 0 && x0 < IMG_W - 1 && y0 >= 0 && y0 < IMG_H - 1) {
        const float* p = img + ((size_t)y0 * IMG_W + x0) * 3;
        const float* q = p + ROWF;
        r.x = w00 * pw(p[0]) + w10 * pw(p[3]) + w01 * pw(q[0]) + w11 * pw(q[3]);
        r.y = w00 * pw(p[1]) + w10 * pw(p[4]) + w01 * pw(q[1]) + w11 * pw(q[4]);
        r.z = w00 * pw(p[2]) + w10 * pw(p[5]) + w01 * pw(q[2]) + w11 * pw(q[5]);
    } else {
        bool vx0 = (x0 >= 0)  && (x0 <= IMG_W - 1);
        bool vx1 = (x0 >= -1) && (x0 <= IMG_W - 2);
        bool vy0 = (y0 >= 0)  && (y0 <= IMG_H - 1);
        bool vy1 = (y0 >= -1) && (y0 <= IMG_H - 2);
        int xc0 = min(max(x0,     0), IMG_W - 1);
        int xc1 = min(max(x0 + 1, 0), IMG_W - 1);
        int yc0 = min(max(y0,     0), IMG_H - 1);
        int yc1 = min(max(y0 + 1, 0), IMG_H - 1);
        const float* p00 = img + ((size_t)yc0 * IMG_W + xc0) * 3;
        const float* p10 = img + ((size_t)yc0 * IMG_W + xc1) * 3;
        const float* p01 = img + ((size_t)yc1 * IMG_W + xc0) * 3;
        const float* p11 = img + ((size_t)yc1 * IMG_W + xc1) * 3;
        bool v00 = vx0 && vy0, v10 = vx1 && vy0, v01 = vx0 && vy1, v11 = vx1 && vy1;
        r.x = w00 * (v00 ? pw(p00[0]) : 0.5f) + w10 * (v10 ? pw(p10[0]) : 0.5f)
            + w01 * (v01 ? pw(p01[0]) : 0.5f) + w11 * (v11 ? pw(p11[0]) : 0.5f);
        r.y = w00 * (v00 ? pw(p00[1]) : 0.5f) + w10 * (v10 ? pw(p10[1]) : 0.5f)
            + w01 * (v01 ? pw(p01[1]) : 0.5f) + w11 * (v11 ? pw(p11[1]) : 0.5f);
        r.z = w00 * (v00 ? pw(p00[2]) : 0.5f) + w10 * (v10 ? pw(p10[2]) : 0.5f)
            + w01 * (v01 ? pw(p01[2]) : 0.5f) + w11 * (v11 ? pw(p11[2]) : 0.5f);
    }
    return r;
}

// ---------------------------------------------------------------------------
// single-pixel sharpness (border/fallback)
// ---------------------------------------------------------------------------
template <class PW>
__device__ __forceinline__ F3 sharp3x3(const float* __restrict__ img,
                                       float f, int x, int y, PW pw)
{
    const float* p = img + ((size_t)y * IMG_W + x) * 3;
    float v0 = pw(p[0]), v1 = pw(p[1]), v2 = pw(p[2]);
    float s0 = 0.f, s1 = 0.f, s2 = 0.f;
    #pragma unroll
    for (int dy = -1; dy <= 1; dy++) {
        int yy = min(max(y + dy, 0), IMG_H - 1);
        #pragma unroll
        for (int dx = -1; dx <= 1; dx++) {
            int xx = min(max(x + dx, 0), IMG_W - 1);
            float k = (dx == 0 && dy == 0) ? (5.0f/13.0f) : (1.0f/13.0f);
            const float* q = img + ((size_t)yy * IMG_W + xx) * 3;
            s0 += k * pw(q[0]); s1 += k * pw(q[1]); s2 += k * pw(q[2]);
        }
    }
    F3 r;
    r.x = fminf(fmaxf(s0 + f * (v0 - s0), 0.f), 1.f);
    r.y = fminf(fmaxf(s1 + f * (v1 - s1), 0.f), 1.f);
    r.z = fminf(fmaxf(s2 + f * (v2 - s2), 0.f), 1.f);
    return r;
}

// ---------------------------------------------------------------------------
// quad-row sharpness: 6 kernel rows (18 taps) for 4 outputs, channel-major
// ---------------------------------------------------------------------------
template <class PW>
__device__ __forceinline__ void sharp4(const float* __restrict__ img,
                                       float f, int x, int y, F3 r[4], PW pw)
{
    if (x >= 1 && x <= IMG_W - 2 && y >= 1 && y + 4 <= IMG_H - 1) {
        const float* base = img + ((size_t)(y - 1) * IMG_W + x) * 3;
        float out[4][3];
        #pragma unroll
        for (int ch = 0; ch < 3; ch++) {
            float R[6], V[6];
            #pragma unroll
            for (int j = 0; j < 6; j++) {
                const float* p = base + (size_t)j * ROWF;
                float l = pw(p[ch - 3]), c = pw(p[ch]), rr = pw(p[ch + 3]);
                V[j] = c;
                R[j] = l + c + rr;
            }
            #pragma unroll
            for (int i = 0; i < 4; i++) {
                float v = V[i + 1];
                float s = (R[i] + R[i+1] + R[i+2] + 4.f * v) * (1.f / 13.f);
                out[i][ch] = fminf(fmaxf(s + f * (v - s), 0.f), 1.f);
            }
        }
        #pragma unroll
        for (int i = 0; i < 4; i++) {
            r[i].x = out[i][0]; r[i].y = out[i][1]; r[i].z = out[i][2];
        }
    } else {
        #pragma unroll
        for (int i = 0; i < 4; i++) r[i] = sharp3x3(img, f, x, y + i, pw);
    }
}

// ---------------------------------------------------------------------------
// quad-row gather dispatch; op image-uniform, pixels (x, y..y+3)
// ---------------------------------------------------------------------------
template <class PW>
__device__ __forceinline__ void apply_gather4(const float* __restrict__ img,
                                              int op, float s, int x, int y,
                                              F3 r[4], PW pw)
{
    const float cx = (IMG_W - 1) * 0.5f, cy = (IMG_H - 1) * 0.5f;
    const float xf = (float)x - cx;
    float yf[4];
    #pragma unroll
    for (int i = 0; i < 4; i++) yf[i] = (float)(y + i) - cy;

    if (op == 0) {
        float th = s * 0.2617993877991494f;
        float co = cosf(th), si = sinf(th);
        #pragma unroll
        for (int i = 0; i < 4; i++)
            r[i] = bilin4(img, co * xf + si * yf[i] + cx,
                               -si * xf + co * yf[i] + cy, pw);
    } else if (op == 1) {
        float sh = -s * 0.15f;
        #pragma unroll
        for (int i = 0; i < 4; i++)
            r[i] = bilin_h(img, xf + sh * yf[i] + cx, y + i, pw);
    } else if (op == 2) {
        float sh = -s * 0.15f;
        float yi[4];
        #pragma unroll
        for (int i = 0; i < 4; i++) yi[i] = yf[i] + sh * xf + cy;
        bilin_v4(img, yi, x, r, pw);
    } else if (op == 3) {
        float t = -s * 0.15f * (float)IMG_W;
        float xi = xf + t + cx;
        #pragma unroll
        for (int i = 0; i < 4; i++)
            r[i] = bilin_h(img, xi, y + i, pw);
    } else if (op == 4) {
        float t = -s * 0.15f * (float)IMG_H;
        float yi[4];
        #pragma unroll
        for (int i = 0; i < 4; i++) yi[i] = yf[i] + t + cy;
        bilin_v4(img, yi, x, r, pw);
    } else {
        float f = (s > 0.f) ? 1.45f : (1.0f / 1.45f);
        sharp4(img, f, x, y, r, pw);
    }
}

// ---------------------------------------------------------------------------
// fusion predicate: op0 pointwise AND op1 gather (affine/sharp) -> pass2-only
// ---------------------------------------------------------------------------
__device__ __forceinline__ bool pw_fused(int op0, int op1)
{
    return (op0 == 5 || op0 == 6) && (op1 < 5 || op1 == 7);
}

// ---------------------------------------------------------------------------
// reduce0: per-image partial sums of original (only op0 == contrast)
// ---------------------------------------------------------------------------
__global__ void reduce0_kernel(const float* __restrict__ in,
                               const int* __restrict__ op_ids)
{
    int b = blockIdx.y;
    if (op_ids[b * 2] != 6) return;
    const float4* img = (const float4*)(in + (size_t)b * NPEL);
    float s = 0.f;
    for (int i = blockIdx.x * 256 + threadIdx.x; i < NPEL / 4; i += RBLK * 256) {
        float4 v = img[i];
        s += v.x + v.y + v.z + v.w;
    }
    __shared__ float sd[256];
    sd[threadIdx.x] = s;
    __syncthreads();
    #pragma unroll
    for (int st = 128; st > 0; st >>= 1) {
        if (threadIdx.x < st) sd[threadIdx.x] += sd[threadIdx.x + st];
        __syncthreads();
    }
    if (threadIdx.x == 0) g_partial0[b * RBLK + blockIdx.x] = sd[0];
}

// ---------------------------------------------------------------------------
// combine1: fold pass1's per-block partials -> g_mean1[b]
// ---------------------------------------------------------------------------
__global__ void combine1_kernel(const int* __restrict__ op_ids)
{
    int b = blockIdx.x;
    if (op_ids[b * 2 + 1] != 6) return;
    __shared__ float sd[256];
    sd[threadIdx.x] = g_partial1[b * P1BLK + threadIdx.x];
    __syncthreads();
    #pragma unroll
    for (int st = 128; st > 0; st >>= 1) {
        if (threadIdx.x < st) sd[threadIdx.x] += sd[threadIdx.x + st];
        __syncthreads();
    }
    if (threadIdx.x == 0) g_mean1[b] = sd[0] * (1.0f / (float)NPEL);
}

// ---------------------------------------------------------------------------
// pass1: layer 0. Skips pw-fused images entirely (pass2 handles them).
// ---------------------------------------------------------------------------
__global__ void pass1_kernel(const float* __restrict__ in,
                             float* __restrict__ out,
                             const int* __restrict__ op_ids,
                             const int* __restrict__ signs)
{
    const int b   = blockIdx.z;
    const int idx = blockIdx.x * blockDim.x + threadIdx.x;   // [0, NPIX/4)

    const int op0 = op_ids[b * 2], op1 = op_ids[b * 2 + 1];
    if (pw_fused(op0, op1)) return;             // pass2 reads original directly

    const float s0 = signs[b * 2]     ? 1.f : -1.f;
    const float s1 = signs[b * 2 + 1] ? 1.f : -1.f;
    const bool  fuse_b   = (op1 == 5);
    const bool  need_sum = (op1 == 6);
    const float f1 = (s1 > 0.f) ? 1.45f : (1.0f / 1.45f);

    const float* img = in + (size_t)b * NPEL;
    float* dstbase = (fuse_b ? out : g_scratch) + (size_t)b * NPEL;

    float acc = 0.f;

    if (op0 == 5 || op0 == 6) {                 // pointwise: float4 streaming
        // (only reached when op1 is brightness or contrast)
        const float f0 = (s0 > 0.f) ? 1.45f : (1.0f / 1.45f);
        const float m0 = (op0 == 6) ? inline_mean(g_partial0, b) : 0.f;
        for (int i = idx; i < NPEL / 4; i += P1BLK * 256) {
            float4 v = ((const float4*)img)[i];
            float t[4] = { v.x, v.y, v.z, v.w };
            #pragma unroll
            for (int k = 0; k < 4; k++) {
                float u = (op0 == 5) ? f0 * t[k] : m0 + f0 * (t[k] - m0);
                t[k] = fminf(fmaxf(u, 0.f), 1.f);
            }
            if (fuse_b) {
                #pragma unroll
                for (int k = 0; k < 4; k++)
                    t[k] = fminf(fmaxf(f1 * t[k], 0.f), 1.f);
            }
            if (need_sum) acc += t[0] + t[1] + t[2] + t[3];
            ((float4*)dstbase)[i] = make_float4(t[0], t[1], t[2], t[3]);
        }
    } else {
        // gather path: quad-row, all threads active
        const int y = (idx >> 9) * 4;
        const int x = idx & (IMG_W - 1);

        F3 r[4];
        apply_gather4(img, op0, s0, x, y, r, PWId());

        if (fuse_b) {
            #pragma unroll
            for (int i = 0; i < 4; i++) {
                r[i].x = fminf(fmaxf(f1 * r[i].x, 0.f), 1.f);
                r[i].y = fminf(fmaxf(f1 * r[i].y, 0.f), 1.f);
                r[i].z = fminf(fmaxf(f1 * r[i].z, 0.f), 1.f);
            }
        }
        if (need_sum) {
            #pragma unroll
            for (int i = 0; i < 4; i++)
                acc += r[i].x + r[i].y + r[i].z;
        }

        float* o = dstbase + ((size_t)y * IMG_W + x) * 3;
        #pragma unroll
        for (int i = 0; i < 4; i++) {
            o[0] = r[i].x; o[1] = r[i].y; o[2] = r[i].z;
            o += ROWF;
        }
    }

    if (need_sum) {                             // image-uniform branch
        __shared__ float sd[256];
        sd[threadIdx.x] = acc;
        __syncthreads();
        #pragma unroll
        for (int st = 128; st > 0; st >>= 1) {
            if (threadIdx.x < st) sd[threadIdx.x] += sd[threadIdx.x + st];
            __syncthreads();
        }
        if (threadIdx.x == 0) g_partial1[b * P1BLK + blockIdx.x] = sd[0];
    }
}

// ---------------------------------------------------------------------------
// pass2: layer 1 -> out.
//  - op1==brightness: done in pass1.
//  - op1==contrast: float4 streaming from scratch with g_mean1.
//  - gather op1, op0 pointwise: taps from ORIGINAL with fused pointwise (PWAff).
//  - gather op1, op0 gather: taps from scratch (PWId).
// ---------------------------------------------------------------------------
__global__ void pass2_kernel(const float* __restrict__ in,
                             float* __restrict__ out,
                             const int* __restrict__ op_ids,
                             const int* __restrict__ signs)
{
    const int b   = blockIdx.z;
    const int op0 = op_ids[b * 2], op1 = op_ids[b * 2 + 1];
    if (op1 == 5) return;                       // fused into pass1

    const int idx = blockIdx.x * blockDim.x + threadIdx.x;   // [0, NPIX/4)
    const float s1 = signs[b * 2 + 1] ? 1.f : -1.f;
    const float f1 = (s1 > 0.f) ? 1.45f : (1.0f / 1.45f);

    float* outb = out + (size_t)b * NPEL;

    if (op1 == 6) {                             // contrast: float4 streaming
        const float* img = g_scratch + (size_t)b * NPEL;
        const float m = g_mean1[b];
        for (int i = idx; i < NPEL / 4; i += NPIX / 4) {
            float4 v = ((const float4*)img)[i];
            float t[4] = { v.x, v.y, v.z, v.w };
            #pragma unroll
            for (int k = 0; k < 4; k++)
                t[k] = fminf(fmaxf(m + f1 * (t[k] - m), 0.f), 1.f);
            ((float4*)outb)[i] = make_float4(t[0], t[1], t[2], t[3]);
        }
        return;
    }

    // gather path: quad-row
    const int y = (idx >> 9) * 4;
    const int x = idx & (IMG_W - 1);

    F3 r[4];
    if (pw_fused(op0, op1)) {
        // taps from original, layer-0 pointwise fused per tap
        const float s0 = signs[b * 2] ? 1.f : -1.f;
        PWAff pw;
        pw.f = (s0 > 0.f) ? 1.45f : (1.0f / 1.45f);
        pw.m = (op0 == 6) ? inline_mean(g_partial0, b) : 0.f;
        apply_gather4(in + (size_t)b * NPEL, op1, s1, x, y, r, pw);
    } else {
        apply_gather4(g_scratch + (size_t)b * NPEL, op1, s1, x, y, r, PWId());
    }

    float* o = outb + ((size_t)y * IMG_W + x) * 3;
    #pragma unroll
    for (int i = 0; i < 4; i++) {
        o[0] = r[i].x; o[1] = r[i].y; o[2] = r[i].z;
        o += ROWF;
    }
}

// ---------------------------------------------------------------------------
extern "C" void kernel_launch(void* const* d_in, const int* in_sizes, int n_in,
                              void* d_out, int out_size)
{
    const float* images = (const float*)d_in[0];
    const int*   op_ids = (const int*)  d_in[1];
    const int*   signs  = (const int*)  d_in[2];
    float*       out    = (float*)d_out;

    dim3 rgrid(RBLK, NB);
    dim3 g1(P1BLK, 1, NB);            // 256 blocks/image
    dim3 g2(NPIX / 4 / 256, 1, NB);   // 256 blocks/image

    reduce0_kernel <<<rgrid, 256>>>(images, op_ids);
    pass1_kernel   <<<g1, 256>>>(images, out, op_ids, signs);
    combine1_kernel<<<NB, 256>>>(op_ids);
    pass2_kernel   <<<g2, 256>>>(images, out, op_ids, signs);
}

// round 15
// speedup vs baseline: 1.2524x; 1.2524x over previous
#include <cuda_runtime.h>
#include <math.h>

#define IMG_H 512
#define IMG_W 512
#define NB    64
#define NPIX  (IMG_H * IMG_W)
#define NPEL  (NPIX * 3)
#define RBLK  64
#define ROWF  (IMG_W * 3)
#define P1BLK 256          // pass blocks per image (= NPIX/4/256)

__device__ float g_scratch[(size_t)NB * NPEL];
__device__ float g_partial0[NB * RBLK];
__device__ float g_partial1[NB * P1BLK];
__device__ float g_mean1[NB];

struct F3 { float x, y, z; };

// pointwise transforms applied per tapped value
struct PWId  {
    __device__ __forceinline__ float operator()(float v) const { return v; }
};
struct PWAff {                       // clip(m + f*(v-m)); m=0 -> brightness
    float f, m;
    __device__ __forceinline__ float operator()(float v) const {
        return fminf(fmaxf(m + f * (v - m), 0.f), 1.f);
    }
};

__device__ __forceinline__ float inline_mean(const float* __restrict__ part, int b)
{
    float s = 0.f;
    #pragma unroll
    for (int i = 0; i < RBLK; i++) s += part[b * RBLK + i];
    return s * (1.0f / (float)NPEL);
}

// ---------------------------------------------------------------------------
// horizontal 2-tap bilinear (wy == 0 exactly)
// ---------------------------------------------------------------------------
template <class PW>
__device__ __forceinline__ F3 bilin_h(const float* __restrict__ img, float xi, int y,
                                      PW pw)
{
    float x0f = floorf(xi);
    float wx  = xi - x0f;
    float w0  = 1.f - wx;
    int   x0  = (int)x0f;
    const float* row = img + (size_t)y * ROWF;
    F3 r;
    if (x0 >= 0 && x0 < IMG_W - 1) {
        const float* p = row + x0 * 3;
        r.x = w0 * pw(p[0]) + wx * pw(p[3]);
        r.y = w0 * pw(p[1]) + wx * pw(p[4]);
        r.z = w0 * pw(p[2]) + wx * pw(p[5]);
    } else {
        bool v0 = (x0 >= 0)  && (x0 <= IMG_W - 1);
        bool v1 = (x0 >= -1) && (x0 <= IMG_W - 2);
        int xc0 = min(max(x0,     0), IMG_W - 1);
        int xc1 = min(max(x0 + 1, 0), IMG_W - 1);
        const float* p0 = row + xc0 * 3;
        const float* p1 = row + xc1 * 3;
        float a0 = v0 ? pw(p0[0]) : 0.5f, a1 = v0 ? pw(p0[1]) : 0.5f, a2 = v0 ? pw(p0[2]) : 0.5f;
        float b0 = v1 ? pw(p1[0]) : 0.5f, b1 = v1 ? pw(p1[1]) : 0.5f, b2 = v1 ? pw(p1[2]) : 0.5f;
        r.x = w0 * a0 + wx * b0;
        r.y = w0 * a1 + wx * b1;
        r.z = w0 * a2 + wx * b2;
    }
    return r;
}

// ---------------------------------------------------------------------------
// vertical 2-tap bilinear, single output (border/fallback)
// ---------------------------------------------------------------------------
template <class PW>
__device__ __forceinline__ F3 bilin_v(const float* __restrict__ img, float yi, int x,
                                      PW pw)
{
    float y0f = floorf(yi);
    float wy  = yi - y0f;
    float w0  = 1.f - wy;
    int   y0  = (int)y0f;
    F3 r;
    if (y0 >= 0 && y0 < IMG_H - 1) {
        const float* p = img + ((size_t)y0 * IMG_W + x) * 3;
        const float* q = p + ROWF;
        r.x = w0 * pw(p[0]) + wy * pw(q[0]);
        r.y = w0 * pw(p[1]) + wy * pw(q[1]);
        r.z = w0 * pw(p[2]) + wy * pw(q[2]);
    } else {
        bool v0 = (y0 >= 0)  && (y0 <= IMG_H - 1);
        bool v1 = (y0 >= -1) && (y0 <= IMG_H - 2);
        int yc0 = min(max(y0,     0), IMG_H - 1);
        int yc1 = min(max(y0 + 1, 0), IMG_H - 1);
        const float* p0 = img + ((size_t)yc0 * IMG_W + x) * 3;
        const float* p1 = img + ((size_t)yc1 * IMG_W + x) * 3;
        float a0 = v0 ? pw(p0[0]) : 0.5f, a1 = v0 ? pw(p0[1]) : 0.5f, a2 = v0 ? pw(p0[2]) : 0.5f;
        float b0 = v1 ? pw(p1[0]) : 0.5f, b1 = v1 ? pw(p1[1]) : 0.5f, b2 = v1 ? pw(p1[2]) : 0.5f;
        r.x = w0 * a0 + wy * b0;
        r.y = w0 * a1 + wy * b1;
        r.z = w0 * a2 + wy * b2;
    }
    return r;
}

// ---------------------------------------------------------------------------
// quad-row vertical bilinear: 5 tap rows for 4 outputs when aligned
// ---------------------------------------------------------------------------
template <class PW>
__device__ __forceinline__ void bilin_v4(const float* __restrict__ img,
                                         const float yi[4], int x, F3 r[4], PW pw)
{
    float k0f = floorf(yi[0]);
    int   k0  = (int)k0f;
    bool aligned = (k0 >= 0) && (k0 + 4 <= IMG_H - 1);
    #pragma unroll
    for (int i = 1; i < 4; i++)
        aligned = aligned && ((int)floorf(yi[i]) == k0 + i);
    if (aligned) {
        const float* p = img + ((size_t)k0 * IMG_W + x) * 3;
        float rv[5][3];
        #pragma unroll
        for (int j = 0; j < 5; j++) {
            rv[j][0] = pw(p[0]); rv[j][1] = pw(p[1]); rv[j][2] = pw(p[2]);
            p += ROWF;
        }
        #pragma unroll
        for (int i = 0; i < 4; i++) {
            float wy = yi[i] - floorf(yi[i]);
            float w0 = 1.f - wy;
            r[i].x = w0 * rv[i][0] + wy * rv[i+1][0];
            r[i].y = w0 * rv[i][1] + wy * rv[i+1][1];
            r[i].z = w0 * rv[i][2] + wy * rv[i+1][2];
        }
    } else {
        #pragma unroll
        for (int i = 0; i < 4; i++) r[i] = bilin_v(img, yi[i], x, pw);
    }
}

// ---------------------------------------------------------------------------
// general 4-tap bilinear (rotate)
// ---------------------------------------------------------------------------
template <class PW>
__device__ __forceinline__ F3 bilin4(const float* __restrict__ img, float xi, float yi,
                                     PW pw)
{
    float x0f = floorf(xi), y0f = floorf(yi);
    float wx = xi - x0f,    wy = yi - y0f;
    int   x0 = (int)x0f,    y0 = (int)y0f;
    float w00 = (1.f - wx) * (1.f - wy);
    float w10 = wx * (1.f - wy);
    float w01 = (1.f - wx) * wy;
    float w11 = wx * wy;
    F3 r;
    if (x0 >= 0 && x0 < IMG_W - 1 && y0 >= 0 && y0 < IMG_H - 1) {
        const float* p = img + ((size_t)y0 * IMG_W + x0) * 3;
        const float* q = p + ROWF;
        r.x = w00 * pw(p[0]) + w10 * pw(p[3]) + w01 * pw(q[0]) + w11 * pw(q[3]);
        r.y = w00 * pw(p[1]) + w10 * pw(p[4]) + w01 * pw(q[1]) + w11 * pw(q[4]);
        r.z = w00 * pw(p[2]) + w10 * pw(p[5]) + w01 * pw(q[2]) + w11 * pw(q[5]);
    } else {
        bool vx0 = (x0 >= 0)  && (x0 <= IMG_W - 1);
        bool vx1 = (x0 >= -1) && (x0 <= IMG_W - 2);
        bool vy0 = (y0 >= 0)  && (y0 <= IMG_H - 1);
        bool vy1 = (y0 >= -1) && (y0 <= IMG_H - 2);
        int xc0 = min(max(x0,     0), IMG_W - 1);
        int xc1 = min(max(x0 + 1, 0), IMG_W - 1);
        int yc0 = min(max(y0,     0), IMG_H - 1);
        int yc1 = min(max(y0 + 1, 0), IMG_H - 1);
        const float* p00 = img + ((size_t)yc0 * IMG_W + xc0) * 3;
        const float* p10 = img + ((size_t)yc0 * IMG_W + xc1) * 3;
        const float* p01 = img + ((size_t)yc1 * IMG_W + xc0) * 3;
        const float* p11 = img + ((size_t)yc1 * IMG_W + xc1) * 3;
        bool v00 = vx0 && vy0, v10 = vx1 && vy0, v01 = vx0 && vy1, v11 = vx1 && vy1;
        r.x = w00 * (v00 ? pw(p00[0]) : 0.5f) + w10 * (v10 ? pw(p10[0]) : 0.5f)
            + w01 * (v01 ? pw(p01[0]) : 0.5f) + w11 * (v11 ? pw(p11[0]) : 0.5f);
        r.y = w00 * (v00 ? pw(p00[1]) : 0.5f) + w10 * (v10 ? pw(p10[1]) : 0.5f)
            + w01 * (v01 ? pw(p01[1]) : 0.5f) + w11 * (v11 ? pw(p11[1]) : 0.5f);
        r.z = w00 * (v00 ? pw(p00[2]) : 0.5f) + w10 * (v10 ? pw(p10[2]) : 0.5f)
            + w01 * (v01 ? pw(p01[2]) : 0.5f) + w11 * (v11 ? pw(p11[2]) : 0.5f);
    }
    return r;
}

// ---------------------------------------------------------------------------
// single-pixel sharpness (border/fallback)
// ---------------------------------------------------------------------------
template <class PW>
__device__ __forceinline__ F3 sharp3x3(const float* __restrict__ img,
                                       float f, int x, int y, PW pw)
{
    const float* p = img + ((size_t)y * IMG_W + x) * 3;
    float v0 = pw(p[0]), v1 = pw(p[1]), v2 = pw(p[2]);
    float s0 = 0.f, s1 = 0.f, s2 = 0.f;
    #pragma unroll
    for (int dy = -1; dy <= 1; dy++) {
        int yy = min(max(y + dy, 0), IMG_H - 1);
        #pragma unroll
        for (int dx = -1; dx <= 1; dx++) {
            int xx = min(max(x + dx, 0), IMG_W - 1);
            float k = (dx == 0 && dy == 0) ? (5.0f/13.0f) : (1.0f/13.0f);
            const float* q = img + ((size_t)yy * IMG_W + xx) * 3;
            s0 += k * pw(q[0]); s1 += k * pw(q[1]); s2 += k * pw(q[2]);
        }
    }
    F3 r;
    r.x = fminf(fmaxf(s0 + f * (v0 - s0), 0.f), 1.f);
    r.y = fminf(fmaxf(s1 + f * (v1 - s1), 0.f), 1.f);
    r.z = fminf(fmaxf(s2 + f * (v2 - s2), 0.f), 1.f);
    return r;
}

// ---------------------------------------------------------------------------
// quad-row sharpness: 6 kernel rows (18 taps) for 4 outputs, channel-major
// ---------------------------------------------------------------------------
template <class PW>
__device__ __forceinline__ void sharp4(const float* __restrict__ img,
                                       float f, int x, int y, F3 r[4], PW pw)
{
    if (x >= 1 && x <= IMG_W - 2 && y >= 1 && y + 4 <= IMG_H - 1) {
        const float* base = img + ((size_t)(y - 1) * IMG_W + x) * 3;
        float out[4][3];
        #pragma unroll
        for (int ch = 0; ch < 3; ch++) {
            float R[6], V[6];
            #pragma unroll
            for (int j = 0; j < 6; j++) {
                const float* p = base + (size_t)j * ROWF;
                float l = pw(p[ch - 3]), c = pw(p[ch]), rr = pw(p[ch + 3]);
                V[j] = c;
                R[j] = l + c + rr;
            }
            #pragma unroll
            for (int i = 0; i < 4; i++) {
                float v = V[i + 1];
                float s = (R[i] + R[i+1] + R[i+2] + 4.f * v) * (1.f / 13.f);
                out[i][ch] = fminf(fmaxf(s + f * (v - s), 0.f), 1.f);
            }
        }
        #pragma unroll
        for (int i = 0; i < 4; i++) {
            r[i].x = out[i][0]; r[i].y = out[i][1]; r[i].z = out[i][2];
        }
    } else {
        #pragma unroll
        for (int i = 0; i < 4; i++) r[i] = sharp3x3(img, f, x, y + i, pw);
    }
}

// ---------------------------------------------------------------------------
// quad-row gather dispatch; op image-uniform, pixels (x, y..y+3)
// ---------------------------------------------------------------------------
template <class PW>
__device__ __forceinline__ void apply_gather4(const float* __restrict__ img,
                                              int op, float s, int x, int y,
                                              F3 r[4], PW pw)
{
    const float cx = (IMG_W - 1) * 0.5f, cy = (IMG_H - 1) * 0.5f;
    const float xf = (float)x - cx;
    float yf[4];
    #pragma unroll
    for (int i = 0; i < 4; i++) yf[i] = (float)(y + i) - cy;

    if (op == 0) {
        float th = s * 0.2617993877991494f;
        float co = cosf(th), si = sinf(th);
        #pragma unroll
        for (int i = 0; i < 4; i++)
            r[i] = bilin4(img, co * xf + si * yf[i] + cx,
                               -si * xf + co * yf[i] + cy, pw);
    } else if (op == 1) {
        float sh = -s * 0.15f;
        #pragma unroll
        for (int i = 0; i < 4; i++)
            r[i] = bilin_h(img, xf + sh * yf[i] + cx, y + i, pw);
    } else if (op == 2) {
        float sh = -s * 0.15f;
        float yi[4];
        #pragma unroll
        for (int i = 0; i < 4; i++) yi[i] = yf[i] + sh * xf + cy;
        bilin_v4(img, yi, x, r, pw);
    } else if (op == 3) {
        float t = -s * 0.15f * (float)IMG_W;
        float xi = xf + t + cx;
        #pragma unroll
        for (int i = 0; i < 4; i++)
            r[i] = bilin_h(img, xi, y + i, pw);
    } else if (op == 4) {
        float t = -s * 0.15f * (float)IMG_H;
        float yi[4];
        #pragma unroll
        for (int i = 0; i < 4; i++) yi[i] = yf[i] + t + cy;
        bilin_v4(img, yi, x, r, pw);
    } else {
        float f = (s > 0.f) ? 1.45f : (1.0f / 1.45f);
        sharp4(img, f, x, y, r, pw);
    }
}

// ---------------------------------------------------------------------------
// fusion predicate: op0 pointwise AND op1 gather -> handled by pass2_fused
// ---------------------------------------------------------------------------
__device__ __forceinline__ bool pw_fused(int op0, int op1)
{
    return (op0 == 5 || op0 == 6) && (op1 < 5 || op1 == 7);
}

// ---------------------------------------------------------------------------
// reduce0: per-image partial sums of original (only op0 == contrast)
// ---------------------------------------------------------------------------
__global__ void reduce0_kernel(const float* __restrict__ in,
                               const int* __restrict__ op_ids)
{
    int b = blockIdx.y;
    if (op_ids[b * 2] != 6) return;
    const float4* img = (const float4*)(in + (size_t)b * NPEL);
    float s = 0.f;
    for (int i = blockIdx.x * 256 + threadIdx.x; i < NPEL / 4; i += RBLK * 256) {
        float4 v = img[i];
        s += v.x + v.y + v.z + v.w;
    }
    __shared__ float sd[256];
    sd[threadIdx.x] = s;
    __syncthreads();
    #pragma unroll
    for (int st = 128; st > 0; st >>= 1) {
        if (threadIdx.x < st) sd[threadIdx.x] += sd[threadIdx.x + st];
        __syncthreads();
    }
    if (threadIdx.x == 0) g_partial0[b * RBLK + blockIdx.x] = sd[0];
}

// ---------------------------------------------------------------------------
// combine1: fold pass1's per-block partials -> g_mean1[b]
// ---------------------------------------------------------------------------
__global__ void combine1_kernel(const int* __restrict__ op_ids)
{
    int b = blockIdx.x;
    if (op_ids[b * 2 + 1] != 6) return;
    __shared__ float sd[256];
    sd[threadIdx.x] = g_partial1[b * P1BLK + threadIdx.x];
    __syncthreads();
    #pragma unroll
    for (int st = 128; st > 0; st >>= 1) {
        if (threadIdx.x < st) sd[threadIdx.x] += sd[threadIdx.x + st];
        __syncthreads();
    }
    if (threadIdx.x == 0) g_mean1[b] = sd[0] * (1.0f / (float)NPEL);
}

// ---------------------------------------------------------------------------
// pass1: layer 0. Skips pw-fused images (handled by pass2_fused).
// PWId instantiation only.
// ---------------------------------------------------------------------------
__global__ void pass1_kernel(const float* __restrict__ in,
                             float* __restrict__ out,
                             const int* __restrict__ op_ids,
                             const int* __restrict__ signs)
{
    const int b   = blockIdx.z;
    const int idx = blockIdx.x * blockDim.x + threadIdx.x;   // [0, NPIX/4)

    const int op0 = op_ids[b * 2], op1 = op_ids[b * 2 + 1];
    if (pw_fused(op0, op1)) return;

    const float s0 = signs[b * 2]     ? 1.f : -1.f;
    const float s1 = signs[b * 2 + 1] ? 1.f : -1.f;
    const bool  fuse_b   = (op1 == 5);
    const bool  need_sum = (op1 == 6);
    const float f1 = (s1 > 0.f) ? 1.45f : (1.0f / 1.45f);

    const float* img = in + (size_t)b * NPEL;
    float* dstbase = (fuse_b ? out : g_scratch) + (size_t)b * NPEL;

    float acc = 0.f;

    if (op0 == 5 || op0 == 6) {                 // pointwise: float4 streaming
        const float f0 = (s0 > 0.f) ? 1.45f : (1.0f / 1.45f);
        const float m0 = (op0 == 6) ? inline_mean(g_partial0, b) : 0.f;
        for (int i = idx; i < NPEL / 4; i += P1BLK * 256) {
            float4 v = ((const float4*)img)[i];
            float t[4] = { v.x, v.y, v.z, v.w };
            #pragma unroll
            for (int k = 0; k < 4; k++) {
                float u = (op0 == 5) ? f0 * t[k] : m0 + f0 * (t[k] - m0);
                t[k] = fminf(fmaxf(u, 0.f), 1.f);
            }
            if (fuse_b) {
                #pragma unroll
                for (int k = 0; k < 4; k++)
                    t[k] = fminf(fmaxf(f1 * t[k], 0.f), 1.f);
            }
            if (need_sum) acc += t[0] + t[1] + t[2] + t[3];
            ((float4*)dstbase)[i] = make_float4(t[0], t[1], t[2], t[3]);
        }
    } else {
        const int y = (idx >> 9) * 4;
        const int x = idx & (IMG_W - 1);

        F3 r[4];
        apply_gather4(img, op0, s0, x, y, r, PWId());

        if (fuse_b) {
            #pragma unroll
            for (int i = 0; i < 4; i++) {
                r[i].x = fminf(fmaxf(f1 * r[i].x, 0.f), 1.f);
                r[i].y = fminf(fmaxf(f1 * r[i].y, 0.f), 1.f);
                r[i].z = fminf(fmaxf(f1 * r[i].z, 0.f), 1.f);
            }
        }
        if (need_sum) {
            #pragma unroll
            for (int i = 0; i < 4; i++)
                acc += r[i].x + r[i].y + r[i].z;
        }

        float* o = dstbase + ((size_t)y * IMG_W + x) * 3;
        #pragma unroll
        for (int i = 0; i < 4; i++) {
            o[0] = r[i].x; o[1] = r[i].y; o[2] = r[i].z;
            o += ROWF;
        }
    }

    if (need_sum) {
        __shared__ float sd[256];
        sd[threadIdx.x] = acc;
        __syncthreads();
        #pragma unroll
        for (int st = 128; st > 0; st >>= 1) {
            if (threadIdx.x < st) sd[threadIdx.x] += sd[threadIdx.x + st];
            __syncthreads();
        }
        if (threadIdx.x == 0) g_partial1[b * P1BLK + blockIdx.x] = sd[0];
    }
}

// ---------------------------------------------------------------------------
// pass2_scratch: layer 1 from scratch -> out for NON-pw-fused images.
// PWId instantiation only — identical body to the proven R12 pass2.
// ---------------------------------------------------------------------------
__global__ void pass2_scratch_kernel(float* __restrict__ out,
                                     const int* __restrict__ op_ids,
                                     const int* __restrict__ signs)
{
    const int b   = blockIdx.z;
    const int op0 = op_ids[b * 2], op1 = op_ids[b * 2 + 1];
    if (op1 == 5 || pw_fused(op0, op1)) return;

    const int idx = blockIdx.x * blockDim.x + threadIdx.x;   // [0, NPIX/4)
    const float s1 = signs[b * 2 + 1] ? 1.f : -1.f;
    const float f1 = (s1 > 0.f) ? 1.45f : (1.0f / 1.45f);

    const float* img = g_scratch + (size_t)b * NPEL;
    float* outb = out + (size_t)b * NPEL;

    if (op1 == 6) {                             // contrast: float4 streaming
        const float m = g_mean1[b];
        for (int i = idx; i < NPEL / 4; i += NPIX / 4) {
            float4 v = ((const float4*)img)[i];
            float t[4] = { v.x, v.y, v.z, v.w };
            #pragma unroll
            for (int k = 0; k < 4; k++)
                t[k] = fminf(fmaxf(m + f1 * (t[k] - m), 0.f), 1.f);
            ((float4*)outb)[i] = make_float4(t[0], t[1], t[2], t[3]);
        }
        return;
    }

    const int y = (idx >> 9) * 4;
    const int x = idx & (IMG_W - 1);

    F3 r[4];
    apply_gather4(img, op1, s1, x, y, r, PWId());

    float* o = outb + ((size_t)y * IMG_W + x) * 3;
    #pragma unroll
    for (int i = 0; i < 4; i++) {
        o[0] = r[i].x; o[1] = r[i].y; o[2] = r[i].z;
        o += ROWF;
    }
}

// ---------------------------------------------------------------------------
// pass2_fused: pw-fused images only — gather from ORIGINAL with per-tap
// layer-0 pointwise (PWAff instantiation only).
// ---------------------------------------------------------------------------
__global__ void pass2_fused_kernel(const float* __restrict__ in,
                                   float* __restrict__ out,
                                   const int* __restrict__ op_ids,
                                   const int* __restrict__ signs)
{
    const int b   = blockIdx.z;
    const int op0 = op_ids[b * 2], op1 = op_ids[b * 2 + 1];
    if (!pw_fused(op0, op1)) return;

    const int idx = blockIdx.x * blockDim.x + threadIdx.x;   // [0, NPIX/4)
    const float s0 = signs[b * 2]     ? 1.f : -1.f;
    const float s1 = signs[b * 2 + 1] ? 1.f : -1.f;

    PWAff pw;
    pw.f = (s0 > 0.f) ? 1.45f : (1.0f / 1.45f);
    pw.m = (op0 == 6) ? inline_mean(g_partial0, b) : 0.f;

    const int y = (idx >> 9) * 4;
    const int x = idx & (IMG_W - 1);

    F3 r[4];
    apply_gather4(in + (size_t)b * NPEL, op1, s1, x, y, r, pw);

    float* o = out + (size_t)b * NPEL + ((size_t)y * IMG_W + x) * 3;
    #pragma unroll
    for (int i = 0; i < 4; i++) {
        o[0] = r[i].x; o[1] = r[i].y; o[2] = r[i].z;
        o += ROWF;
    }
}

// ---------------------------------------------------------------------------
extern "C" void kernel_launch(void* const* d_in, const int* in_sizes, int n_in,
                              void* d_out, int out_size)
{
    const float* images = (const float*)d_in[0];
    const int*   op_ids = (const int*)  d_in[1];
    const int*   signs  = (const int*)  d_in[2];
    float*       out    = (float*)d_out;

    dim3 rgrid(RBLK, NB);
    dim3 gp(P1BLK, 1, NB);            // 256 blocks/image

    reduce0_kernel     <<<rgrid, 256>>>(images, op_ids);
    pass1_kernel       <<<gp, 256>>>(images, out, op_ids, signs);
    combine1_kernel    <<<NB, 256>>>(op_ids);
    pass2_scratch_kernel<<<gp, 256>>>(out, op_ids, signs);
    pass2_fused_kernel <<<gp, 256>>>(images, out, op_ids, signs);
}

// round 16
// speedup vs baseline: 1.2621x; 1.0077x over previous
#include <cuda_runtime.h>
#include <math.h>

#define IMG_H 512
#define IMG_W 512
#define NB    64
#define NPIX  (IMG_H * IMG_W)
#define NPEL  (NPIX * 3)
#define RBLK  64
#define ROWF  (IMG_W * 3)
#define P1BLK 256          // pass blocks per image (= NPIX/4/256)

__device__ float g_scratch[(size_t)NB * NPEL];
__device__ float g_partial0[NB * RBLK];
__device__ float g_partial1[NB * P1BLK];
__device__ float g_mean1[NB];

struct F3 { float x, y, z; };

// pointwise transforms applied per tapped value
struct PWId  {
    __device__ __forceinline__ float operator()(float v) const { return v; }
};
struct PWAff {                       // clip(m + f*(v-m)); m=0 -> brightness
    float f, m;
    __device__ __forceinline__ float operator()(float v) const {
        return fminf(fmaxf(m + f * (v - m), 0.f), 1.f);
    }
};

__device__ __forceinline__ float inline_mean(const float* __restrict__ part, int b)
{
    float s = 0.f;
    #pragma unroll
    for (int i = 0; i < RBLK; i++) s += part[b * RBLK + i];
    return s * (1.0f / (float)NPEL);
}

// ---------------------------------------------------------------------------
// horizontal 2-tap bilinear (wy == 0 exactly)
// ---------------------------------------------------------------------------
template <class PW>
__device__ __forceinline__ F3 bilin_h(const float* __restrict__ img, float xi, int y,
                                      PW pw)
{
    float x0f = floorf(xi);
    float wx  = xi - x0f;
    float w0  = 1.f - wx;
    int   x0  = (int)x0f;
    const float* row = img + (size_t)y * ROWF;
    F3 r;
    if (x0 >= 0 && x0 < IMG_W - 1) {
        const float* p = row + x0 * 3;
        r.x = w0 * pw(p[0]) + wx * pw(p[3]);
        r.y = w0 * pw(p[1]) + wx * pw(p[4]);
        r.z = w0 * pw(p[2]) + wx * pw(p[5]);
    } else {
        bool v0 = (x0 >= 0)  && (x0 <= IMG_W - 1);
        bool v1 = (x0 >= -1) && (x0 <= IMG_W - 2);
        int xc0 = min(max(x0,     0), IMG_W - 1);
        int xc1 = min(max(x0 + 1, 0), IMG_W - 1);
        const float* p0 = row + xc0 * 3;
        const float* p1 = row + xc1 * 3;
        float a0 = v0 ? pw(p0[0]) : 0.5f, a1 = v0 ? pw(p0[1]) : 0.5f, a2 = v0 ? pw(p0[2]) : 0.5f;
        float b0 = v1 ? pw(p1[0]) : 0.5f, b1 = v1 ? pw(p1[1]) : 0.5f, b2 = v1 ? pw(p1[2]) : 0.5f;
        r.x = w0 * a0 + wx * b0;
        r.y = w0 * a1 + wx * b1;
        r.z = w0 * a2 + wx * b2;
    }
    return r;
}

// ---------------------------------------------------------------------------
// vertical 2-tap bilinear, single output (border/fallback)
// ---------------------------------------------------------------------------
template <class PW>
__device__ __forceinline__ F3 bilin_v(const float* __restrict__ img, float yi, int x,
                                      PW pw)
{
    float y0f = floorf(yi);
    float wy  = yi - y0f;
    float w0  = 1.f - wy;
    int   y0  = (int)y0f;
    F3 r;
    if (y0 >= 0 && y0 < IMG_H - 1) {
        const float* p = img + ((size_t)y0 * IMG_W + x) * 3;
        const float* q = p + ROWF;
        r.x = w0 * pw(p[0]) + wy * pw(q[0]);
        r.y = w0 * pw(p[1]) + wy * pw(q[1]);
        r.z = w0 * pw(p[2]) + wy * pw(q[2]);
    } else {
        bool v0 = (y0 >= 0)  && (y0 <= IMG_H - 1);
        bool v1 = (y0 >= -1) && (y0 <= IMG_H - 2);
        int yc0 = min(max(y0,     0), IMG_H - 1);
        int yc1 = min(max(y0 + 1, 0), IMG_H - 1);
        const float* p0 = img + ((size_t)yc0 * IMG_W + x) * 3;
        const float* p1 = img + ((size_t)yc1 * IMG_W + x) * 3;
        float a0 = v0 ? pw(p0[0]) : 0.5f, a1 = v0 ? pw(p0[1]) : 0.5f, a2 = v0 ? pw(p0[2]) : 0.5f;
        float b0 = v1 ? pw(p1[0]) : 0.5f, b1 = v1 ? pw(p1[1]) : 0.5f, b2 = v1 ? pw(p1[2]) : 0.5f;
        r.x = w0 * a0 + wy * b0;
        r.y = w0 * a1 + wy * b1;
        r.z = w0 * a2 + wy * b2;
    }
    return r;
}

// ---------------------------------------------------------------------------
// quad-row vertical bilinear: 5 tap rows for 4 outputs when aligned
// ---------------------------------------------------------------------------
template <class PW>
__device__ __forceinline__ void bilin_v4(const float* __restrict__ img,
                                         const float yi[4], int x, F3 r[4], PW pw)
{
    float k0f = floorf(yi[0]);
    int   k0  = (int)k0f;
    bool aligned = (k0 >= 0) && (k0 + 4 <= IMG_H - 1);
    #pragma unroll
    for (int i = 1; i < 4; i++)
        aligned = aligned && ((int)floorf(yi[i]) == k0 + i);
    if (aligned) {
        const float* p = img + ((size_t)k0 * IMG_W + x) * 3;
        float rv[5][3];
        #pragma unroll
        for (int j = 0; j < 5; j++) {
            rv[j][0] = pw(p[0]); rv[j][1] = pw(p[1]); rv[j][2] = pw(p[2]);
            p += ROWF;
        }
        #pragma unroll
        for (int i = 0; i < 4; i++) {
            float wy = yi[i] - floorf(yi[i]);
            float w0 = 1.f - wy;
            r[i].x = w0 * rv[i][0] + wy * rv[i+1][0];
            r[i].y = w0 * rv[i][1] + wy * rv[i+1][1];
            r[i].z = w0 * rv[i][2] + wy * rv[i+1][2];
        }
    } else {
        #pragma unroll
        for (int i = 0; i < 4; i++) r[i] = bilin_v(img, yi[i], x, pw);
    }
}

// ---------------------------------------------------------------------------
// general 4-tap bilinear (rotate)
// ---------------------------------------------------------------------------
template <class PW>
__device__ __forceinline__ F3 bilin4(const float* __restrict__ img, float xi, float yi,
                                     PW pw)
{
    float x0f = floorf(xi), y0f = floorf(yi);
    float wx = xi - x0f,    wy = yi - y0f;
    int   x0 = (int)x0f,    y0 = (int)y0f;
    float w00 = (1.f - wx) * (1.f - wy);
    float w10 = wx * (1.f - wy);
    float w01 = (1.f - wx) * wy;
    float w11 = wx * wy;
    F3 r;
    if (x0 >= 0 && x0 < IMG_W - 1 && y0 >= 0 && y0 < IMG_H - 1) {
        const float* p = img + ((size_t)y0 * IMG_W + x0) * 3;
        const float* q = p + ROWF;
        r.x = w00 * pw(p[0]) + w10 * pw(p[3]) + w01 * pw(q[0]) + w11 * pw(q[3]);
        r.y = w00 * pw(p[1]) + w10 * pw(p[4]) + w01 * pw(q[1]) + w11 * pw(q[4]);
        r.z = w00 * pw(p[2]) + w10 * pw(p[5]) + w01 * pw(q[2]) + w11 * pw(q[5]);
    } else {
        bool vx0 = (x0 >= 0)  && (x0 <= IMG_W - 1);
        bool vx1 = (x0 >= -1) && (x0 <= IMG_W - 2);
        bool vy0 = (y0 >= 0)  && (y0 <= IMG_H - 1);
        bool vy1 = (y0 >= -1) && (y0 <= IMG_H - 2);
        int xc0 = min(max(x0,     0), IMG_W - 1);
        int xc1 = min(max(x0 + 1, 0), IMG_W - 1);
        int yc0 = min(max(y0,     0), IMG_H - 1);
        int yc1 = min(max(y0 + 1, 0), IMG_H - 1);
        const float* p00 = img + ((size_t)yc0 * IMG_W + xc0) * 3;
        const float* p10 = img + ((size_t)yc0 * IMG_W + xc1) * 3;
        const float* p01 = img + ((size_t)yc1 * IMG_W + xc0) * 3;
        const float* p11 = img + ((size_t)yc1 * IMG_W + xc1) * 3;
        bool v00 = vx0 && vy0, v10 = vx1 && vy0, v01 = vx0 && vy1, v11 = vx1 && vy1;
        r.x = w00 * (v00 ? pw(p00[0]) : 0.5f) + w10 * (v10 ? pw(p10[0]) : 0.5f)
            + w01 * (v01 ? pw(p01[0]) : 0.5f) + w11 * (v11 ? pw(p11[0]) : 0.5f);
        r.y = w00 * (v00 ? pw(p00[1]) : 0.5f) + w10 * (v10 ? pw(p10[1]) : 0.5f)
            + w01 * (v01 ? pw(p01[1]) : 0.5f) + w11 * (v11 ? pw(p11[1]) : 0.5f);
        r.z = w00 * (v00 ? pw(p00[2]) : 0.5f) + w10 * (v10 ? pw(p10[2]) : 0.5f)
            + w01 * (v01 ? pw(p01[2]) : 0.5f) + w11 * (v11 ? pw(p11[2]) : 0.5f);
    }
    return r;
}

// ---------------------------------------------------------------------------
// single-pixel sharpness (border/fallback)
// ---------------------------------------------------------------------------
template <class PW>
__device__ __forceinline__ F3 sharp3x3(const float* __restrict__ img,
                                       float f, int x, int y, PW pw)
{
    const float* p = img + ((size_t)y * IMG_W + x) * 3;
    float v0 = pw(p[0]), v1 = pw(p[1]), v2 = pw(p[2]);
    float s0 = 0.f, s1 = 0.f, s2 = 0.f;
    #pragma unroll
    for (int dy = -1; dy <= 1; dy++) {
        int yy = min(max(y + dy, 0), IMG_H - 1);
        #pragma unroll
        for (int dx = -1; dx <= 1; dx++) {
            int xx = min(max(x + dx, 0), IMG_W - 1);
            float k = (dx == 0 && dy == 0) ? (5.0f/13.0f) : (1.0f/13.0f);
            const float* q = img + ((size_t)yy * IMG_W + xx) * 3;
            s0 += k * pw(q[0]); s1 += k * pw(q[1]); s2 += k * pw(q[2]);
        }
    }
    F3 r;
    r.x = fminf(fmaxf(s0 + f * (v0 - s0), 0.f), 1.f);
    r.y = fminf(fmaxf(s1 + f * (v1 - s1), 0.f), 1.f);
    r.z = fminf(fmaxf(s2 + f * (v2 - s2), 0.f), 1.f);
    return r;
}

// ---------------------------------------------------------------------------
// quad-row sharpness: 6 kernel rows (18 taps) for 4 outputs, channel-major
// ---------------------------------------------------------------------------
template <class PW>
__device__ __forceinline__ void sharp4(const float* __restrict__ img,
                                       float f, int x, int y, F3 r[4], PW pw)
{
    if (x >= 1 && x <= IMG_W - 2 && y >= 1 && y + 4 <= IMG_H - 1) {
        const float* base = img + ((size_t)(y - 1) * IMG_W + x) * 3;
        float out[4][3];
        #pragma unroll
        for (int ch = 0; ch < 3; ch++) {
            float R[6], V[6];
            #pragma unroll
            for (int j = 0; j < 6; j++) {
                const float* p = base + (size_t)j * ROWF;
                float l = pw(p[ch - 3]), c = pw(p[ch]), rr = pw(p[ch + 3]);
                V[j] = c;
                R[j] = l + c + rr;
            }
            #pragma unroll
            for (int i = 0; i < 4; i++) {
                float v = V[i + 1];
                float s = (R[i] + R[i+1] + R[i+2] + 4.f * v) * (1.f / 13.f);
                out[i][ch] = fminf(fmaxf(s + f * (v - s), 0.f), 1.f);
            }
        }
        #pragma unroll
        for (int i = 0; i < 4; i++) {
            r[i].x = out[i][0]; r[i].y = out[i][1]; r[i].z = out[i][2];
        }
    } else {
        #pragma unroll
        for (int i = 0; i < 4; i++) r[i] = sharp3x3(img, f, x, y + i, pw);
    }
}

// ---------------------------------------------------------------------------
// quad-row gather dispatch; op image-uniform, pixels (x, y..y+3)
// ---------------------------------------------------------------------------
template <class PW>
__device__ __forceinline__ void apply_gather4(const float* __restrict__ img,
                                              int op, float s, int x, int y,
                                              F3 r[4], PW pw)
{
    const float cx = (IMG_W - 1) * 0.5f, cy = (IMG_H - 1) * 0.5f;
    const float xf = (float)x - cx;
    float yf[4];
    #pragma unroll
    for (int i = 0; i < 4; i++) yf[i] = (float)(y + i) - cy;

    if (op == 0) {
        float th = s * 0.2617993877991494f;
        float co = cosf(th), si = sinf(th);
        #pragma unroll
        for (int i = 0; i < 4; i++)
            r[i] = bilin4(img, co * xf + si * yf[i] + cx,
                               -si * xf + co * yf[i] + cy, pw);
    } else if (op == 1) {
        float sh = -s * 0.15f;
        #pragma unroll
        for (int i = 0; i < 4; i++)
            r[i] = bilin_h(img, xf + sh * yf[i] + cx, y + i, pw);
    } else if (op == 2) {
        float sh = -s * 0.15f;
        float yi[4];
        #pragma unroll
        for (int i = 0; i < 4; i++) yi[i] = yf[i] + sh * xf + cy;
        bilin_v4(img, yi, x, r, pw);
    } else if (op == 3) {
        float t = -s * 0.15f * (float)IMG_W;
        float xi = xf + t + cx;
        #pragma unroll
        for (int i = 0; i < 4; i++)
            r[i] = bilin_h(img, xi, y + i, pw);
    } else if (op == 4) {
        float t = -s * 0.15f * (float)IMG_H;
        float yi[4];
        #pragma unroll
        for (int i = 0; i < 4; i++) yi[i] = yf[i] + t + cy;
        bilin_v4(img, yi, x, r, pw);
    } else {
        float f = (s > 0.f) ? 1.45f : (1.0f / 1.45f);
        sharp4(img, f, x, y, r, pw);
    }
}

// ---------------------------------------------------------------------------
// fusion predicate: op0 pointwise AND op1 gather -> handled by pass2_fused
// ---------------------------------------------------------------------------
__device__ __forceinline__ bool pw_fused(int op0, int op1)
{
    return (op0 == 5 || op0 == 6) && (op1 < 5 || op1 == 7);
}

// ---------------------------------------------------------------------------
// reduce0: per-image partial sums of original (only op0 == contrast)
// ---------------------------------------------------------------------------
__global__ void reduce0_kernel(const float* __restrict__ in,
                               const int* __restrict__ op_ids)
{
    int b = blockIdx.y;
    if (op_ids[b * 2] != 6) return;
    const float4* img = (const float4*)(in + (size_t)b * NPEL);
    float s = 0.f;
    for (int i = blockIdx.x * 256 + threadIdx.x; i < NPEL / 4; i += RBLK * 256) {
        float4 v = img[i];
        s += v.x + v.y + v.z + v.w;
    }
    __shared__ float sd[256];
    sd[threadIdx.x] = s;
    __syncthreads();
    #pragma unroll
    for (int st = 128; st > 0; st >>= 1) {
        if (threadIdx.x < st) sd[threadIdx.x] += sd[threadIdx.x + st];
        __syncthreads();
    }
    if (threadIdx.x == 0) g_partial0[b * RBLK + blockIdx.x] = sd[0];
}

// ---------------------------------------------------------------------------
// combine1: fold pass1's per-block partials -> g_mean1[b]
// ---------------------------------------------------------------------------
__global__ void combine1_kernel(const int* __restrict__ op_ids)
{
    int b = blockIdx.x;
    if (op_ids[b * 2 + 1] != 6) return;
    __shared__ float sd[256];
    sd[threadIdx.x] = g_partial1[b * P1BLK + threadIdx.x];
    __syncthreads();
    #pragma unroll
    for (int st = 128; st > 0; st >>= 1) {
        if (threadIdx.x < st) sd[threadIdx.x] += sd[threadIdx.x + st];
        __syncthreads();
    }
    if (threadIdx.x == 0) g_mean1[b] = sd[0] * (1.0f / (float)NPEL);
}

// ---------------------------------------------------------------------------
// pass1: layer 0. Skips pw-fused images (handled by pass2_fused).
// PWId instantiation only.
// ---------------------------------------------------------------------------
__global__ void pass1_kernel(const float* __restrict__ in,
                             float* __restrict__ out,
                             const int* __restrict__ op_ids,
                             const int* __restrict__ signs)
{
    const int b   = blockIdx.z;
    const int idx = blockIdx.x * blockDim.x + threadIdx.x;   // [0, NPIX/4)

    const int op0 = op_ids[b * 2], op1 = op_ids[b * 2 + 1];
    if (pw_fused(op0, op1)) return;

    const float s0 = signs[b * 2]     ? 1.f : -1.f;
    const float s1 = signs[b * 2 + 1] ? 1.f : -1.f;
    const bool  fuse_b   = (op1 == 5);
    const bool  need_sum = (op1 == 6);
    const float f1 = (s1 > 0.f) ? 1.45f : (1.0f / 1.45f);

    const float* img = in + (size_t)b * NPEL;
    float* dstbase = (fuse_b ? out : g_scratch) + (size_t)b * NPEL;

    float acc = 0.f;

    if (op0 == 5 || op0 == 6) {                 // pointwise: float4 streaming
        const float f0 = (s0 > 0.f) ? 1.45f : (1.0f / 1.45f);
        const float m0 = (op0 == 6) ? inline_mean(g_partial0, b) : 0.f;
        for (int i = idx; i < NPEL / 4; i += P1BLK * 256) {
            float4 v = ((const float4*)img)[i];
            float t[4] = { v.x, v.y, v.z, v.w };
            #pragma unroll
            for (int k = 0; k < 4; k++) {
                float u = (op0 == 5) ? f0 * t[k] : m0 + f0 * (t[k] - m0);
                t[k] = fminf(fmaxf(u, 0.f), 1.f);
            }
            if (fuse_b) {
                #pragma unroll
                for (int k = 0; k < 4; k++)
                    t[k] = fminf(fmaxf(f1 * t[k], 0.f), 1.f);
            }
            if (need_sum) acc += t[0] + t[1] + t[2] + t[3];
            ((float4*)dstbase)[i] = make_float4(t[0], t[1], t[2], t[3]);
        }
    } else {
        const int y = (idx >> 9) * 4;
        const int x = idx & (IMG_W - 1);

        F3 r[4];
        apply_gather4(img, op0, s0, x, y, r, PWId());

        if (fuse_b) {
            #pragma unroll
            for (int i = 0; i < 4; i++) {
                r[i].x = fminf(fmaxf(f1 * r[i].x, 0.f), 1.f);
                r[i].y = fminf(fmaxf(f1 * r[i].y, 0.f), 1.f);
                r[i].z = fminf(fmaxf(f1 * r[i].z, 0.f), 1.f);
            }
        }
        if (need_sum) {
            #pragma unroll
            for (int i = 0; i < 4; i++)
                acc += r[i].x + r[i].y + r[i].z;
        }

        float* o = dstbase + ((size_t)y * IMG_W + x) * 3;
        #pragma unroll
        for (int i = 0; i < 4; i++) {
            o[0] = r[i].x; o[1] = r[i].y; o[2] = r[i].z;
            o += ROWF;
        }
    }

    if (need_sum) {
        __shared__ float sd[256];
        sd[threadIdx.x] = acc;
        __syncthreads();
        #pragma unroll
        for (int st = 128; st > 0; st >>= 1) {
            if (threadIdx.x < st) sd[threadIdx.x] += sd[threadIdx.x + st];
            __syncthreads();
        }
        if (threadIdx.x == 0) g_partial1[b * P1BLK + blockIdx.x] = sd[0];
    }
}

// ---------------------------------------------------------------------------
// pass2_scratch: layer 1 from scratch -> out for NON-pw-fused images.
// PWId instantiation only.
// ---------------------------------------------------------------------------
__global__ void pass2_scratch_kernel(float* __restrict__ out,
                                     const int* __restrict__ op_ids,
                                     const int* __restrict__ signs)
{
    const int b   = blockIdx.z;
    const int op0 = op_ids[b * 2], op1 = op_ids[b * 2 + 1];
    if (op1 == 5 || pw_fused(op0, op1)) return;

    const int idx = blockIdx.x * blockDim.x + threadIdx.x;   // [0, NPIX/4)
    const float s1 = signs[b * 2 + 1] ? 1.f : -1.f;
    const float f1 = (s1 > 0.f) ? 1.45f : (1.0f / 1.45f);

    const float* img = g_scratch + (size_t)b * NPEL;
    float* outb = out + (size_t)b * NPEL;

    if (op1 == 6) {                             // contrast: float4 streaming
        const float m = g_mean1[b];
        for (int i = idx; i < NPEL / 4; i += NPIX / 4) {
            float4 v = ((const float4*)img)[i];
            float t[4] = { v.x, v.y, v.z, v.w };
            #pragma unroll
            for (int k = 0; k < 4; k++)
                t[k] = fminf(fmaxf(m + f1 * (t[k] - m), 0.f), 1.f);
            ((float4*)outb)[i] = make_float4(t[0], t[1], t[2], t[3]);
        }
        return;
    }

    const int y = (idx >> 9) * 4;
    const int x = idx & (IMG_W - 1);

    F3 r[4];
    apply_gather4(img, op1, s1, x, y, r, PWId());

    float* o = outb + ((size_t)y * IMG_W + x) * 3;
    #pragma unroll
    for (int i = 0; i < 4; i++) {
        o[0] = r[i].x; o[1] = r[i].y; o[2] = r[i].z;
        o += ROWF;
    }
}

// ---------------------------------------------------------------------------
// pass2_fused: pw-fused images only — gather from ORIGINAL with per-tap
// layer-0 pointwise (PWAff instantiation only). Depends only on reduce0.
// ---------------------------------------------------------------------------
__global__ void pass2_fused_kernel(const float* __restrict__ in,
                                   float* __restrict__ out,
                                   const int* __restrict__ op_ids,
                                   const int* __restrict__ signs)
{
    const int b   = blockIdx.z;
    const int op0 = op_ids[b * 2], op1 = op_ids[b * 2 + 1];
    if (!pw_fused(op0, op1)) return;

    const int idx = blockIdx.x * blockDim.x + threadIdx.x;   // [0, NPIX/4)
    const float s0 = signs[b * 2]     ? 1.f : -1.f;
    const float s1 = signs[b * 2 + 1] ? 1.f : -1.f;

    PWAff pw;
    pw.f = (s0 > 0.f) ? 1.45f : (1.0f / 1.45f);
    pw.m = (op0 == 6) ? inline_mean(g_partial0, b) : 0.f;

    const int y = (idx >> 9) * 4;
    const int x = idx & (IMG_W - 1);

    F3 r[4];
    apply_gather4(in + (size_t)b * NPEL, op1, s1, x, y, r, pw);

    float* o = out + (size_t)b * NPEL + ((size_t)y * IMG_W + x) * 3;
    #pragma unroll
    for (int i = 0; i < 4; i++) {
        o[0] = r[i].x; o[1] = r[i].y; o[2] = r[i].z;
        o += ROWF;
    }
}

// ---------------------------------------------------------------------------
// Launch: fork pass2_fused onto a side stream after reduce0 so it overlaps
// pass1 / combine1 / pass2_scratch (disjoint image sets). Standard captured
// event fork/join; streams+events are host resources (created per call —
// kernel_launch only runs a handful of times pre-capture).
// ---------------------------------------------------------------------------
extern "C" void kernel_launch(void* const* d_in, const int* in_sizes, int n_in,
                              void* d_out, int out_size)
{
    const float* images = (const float*)d_in[0];
    const int*   op_ids = (const int*)  d_in[1];
    const int*   signs  = (const int*)  d_in[2];
    float*       out    = (float*)d_out;

    dim3 rgrid(RBLK, NB);
    dim3 gp(P1BLK, 1, NB);            // 256 blocks/image

    cudaStream_t s2;
    cudaEvent_t  evFork, evJoin;
    cudaStreamCreateWithFlags(&s2, cudaStreamNonBlocking);
    cudaEventCreateWithFlags(&evFork, cudaEventDisableTiming);
    cudaEventCreateWithFlags(&evJoin, cudaEventDisableTiming);

    reduce0_kernel<<<rgrid, 256>>>(images, op_ids);

    // fork: pass2_fused depends only on reduce0
    cudaEventRecord(evFork, 0);
    cudaStreamWaitEvent(s2, evFork, 0);
    pass2_fused_kernel<<<gp, 256, 0, s2>>>(images, out, op_ids, signs);

    // main chain
    pass1_kernel        <<<gp, 256>>>(images, out, op_ids, signs);
    combine1_kernel     <<<NB, 256>>>(op_ids);
    pass2_scratch_kernel<<<gp, 256>>>(out, op_ids, signs);

    // join before capture ends
    cudaEventRecord(evJoin, s2);
    cudaStreamWaitEvent(0, evJoin, 0);
}